// round 5
// baseline (speedup 1.0000x reference)
#include <cuda_runtime.h>

#define NBINS 20
#define NHALF 10
#define NACC  (2 * NBINS)   // g_acc[0..19] = sum w ; g_acc[20..39] = sum w*(p-t)

__device__ double g_acc[NACC];
__device__ unsigned int g_count;

// ---- packed f32x2 helpers (Blackwell FFMA2 path, PTX-only) ----
__device__ __forceinline__ unsigned long long pk2(float lo, float hi) {
    unsigned long long r;
    asm("mov.b64 %0, {%1, %2};" : "=l"(r)
        : "r"(__float_as_uint(lo)), "r"(__float_as_uint(hi)));
    return r;
}
__device__ __forceinline__ void upk2(unsigned long long v, float& lo, float& hi) {
    unsigned int a, b;
    asm("mov.b64 {%0, %1}, %2;" : "=r"(a), "=r"(b) : "l"(v));
    lo = __uint_as_float(a);
    hi = __uint_as_float(b);
}
__device__ __forceinline__ unsigned long long fma2(unsigned long long a,
                                                   unsigned long long b,
                                                   unsigned long long c) {
    unsigned long long d;
    asm("fma.rn.f32x2 %0, %1, %2, %3;" : "=l"(d) : "l"(a), "l"(b), "l"(c));
    return d;
}
__device__ __forceinline__ unsigned long long add2(unsigned long long a,
                                                   unsigned long long b) {
    unsigned long long d;
    asm("add.rn.f32x2 %0, %1, %2;" : "=l"(d) : "l"(a), "l"(b));
    return d;
}
__device__ __forceinline__ unsigned long long mul2(unsigned long long a,
                                                   unsigned long long b) {
    unsigned long long d;
    asm("mul.rn.f32x2 %0, %1, %2;" : "=l"(d) : "l"(a), "l"(b));
    return d;
}

// delta = 1/19, T = 0.1:
//   r          = exp(2*delta*p/T)  = exp(p * 20/19)
//   lane0 seed = exp(-p^2/T)       = exp(-10 p^2)
//   lane1 seed = seed * r^10       = exp(-10 p^2 + p * 200/19)   (direct MUFU)
#define KR   (20.0f / 19.0f)
#define KR10 (200.0f / 19.0f)

__global__ void __launch_bounds__(128, 8)
ace_fused_kernel(const float* __restrict__ preds,
                 const float* __restrict__ targs,
                 int n, float* __restrict__ out, int out_size) {
    // Packed accumulators: lane0 = bin j, lane1 = bin j+10.
    unsigned long long A2[NHALF], D2[NHALF];
#pragma unroll
    for (int j = 0; j < NHALF; j++) { A2[j] = 0ull; D2[j] = 0ull; }

    const int n4 = n >> 2;
    const float4* p4 = (const float4*)preds;
    const float4* t4 = (const float4*)targs;
    const int stride = gridDim.x * blockDim.x;

    for (int g = blockIdx.x * blockDim.x + threadIdx.x; g < n4; g += stride) {
        float4 pv = p4[g];
        float4 tv = t4[g];

        // one element at a time: minimal live state, max CTAs/SM
#pragma unroll
        for (int e = 0; e < 4; e++) {
            float p = (e == 0) ? pv.x : (e == 1) ? pv.y : (e == 2) ? pv.z : pv.w;
            float t = (e == 0) ? tv.x : (e == 1) ? tv.y : (e == 2) ? tv.z : tv.w;

            float q = p * p;
            float s_lo = __expf(-10.0f * q);
            float s_hi = __expf(fmaf(KR10, p, -10.0f * q));
            float r    = __expf(KR * p);
            float d    = p - t;

            unsigned long long s  = pk2(s_lo, s_hi);
            unsigned long long rr = pk2(r, r);
            unsigned long long dd = pk2(d, d);

#pragma unroll
            for (int j = 0; j < NHALF; j++) {
                A2[j] = add2(A2[j], s);
                D2[j] = fma2(s, dd, D2[j]);
                if (j < NHALF - 1) s = mul2(s, rr);
            }
        }
    }

    // ---- scalar tail (n % 4; empty for this shape) ----
    {
        int base4 = n4 << 2;
        int rem = n - base4;
        if (blockIdx.x == 0 && threadIdx.x < rem) {
            float p0 = preds[base4 + threadIdx.x];
            float t0 = targs[base4 + threadIdx.x];
            float s = __expf(-10.0f * p0 * p0);
            float r = __expf(KR * p0);
            float d = p0 - t0;
            for (int j = 0; j < NBINS; j++) {
                atomicAdd(&g_acc[j],         (double)s);
                atomicAdd(&g_acc[NBINS + j], (double)(s * d));
                s *= r;
            }
        }
    }

    // ---- block reduction: warp shuffles, then shared across warps ----
    __shared__ float sh[4][NACC];
    int lane = threadIdx.x & 31;
    int warp = threadIdx.x >> 5;

#pragma unroll
    for (int j = 0; j < NHALF; j++) {
        float alo, ahi, dlo, dhi;
        upk2(A2[j], alo, ahi);
        upk2(D2[j], dlo, dhi);
        float v[4] = {alo, ahi, dlo, dhi};
        // bin indices: A: j, j+10 ; D: 20+j, 30+j
        int idx[4] = {j, j + NHALF, NBINS + j, NBINS + NHALF + j};
#pragma unroll
        for (int q = 0; q < 4; q++) {
            float s = v[q];
#pragma unroll
            for (int off = 16; off; off >>= 1)
                s += __shfl_down_sync(0xffffffffu, s, off);
            if (lane == 0) sh[warp][idx[q]] = s;
        }
    }
    __syncthreads();

    if (threadIdx.x < NACC) {
        double v = (double)sh[0][threadIdx.x] + (double)sh[1][threadIdx.x] +
                   (double)sh[2][threadIdx.x] + (double)sh[3][threadIdx.x];
        atomicAdd(&g_acc[threadIdx.x], v);
    }
    __syncthreads();

    // ---- last block finalizes, writes out, resets state ----
    __shared__ unsigned int s_is_last;
    if (threadIdx.x == 0) {
        __threadfence();
        unsigned int old = atomicAdd(&g_count, 1u);
        s_is_last = (old == gridDim.x - 1) ? 1u : 0u;
    }
    __syncthreads();

    if (s_is_last && threadIdx.x == 0) {
        __threadfence();
        double loss = 0.0;
        for (int j = 0; j < NBINS; j++) {
            double c = (double)j / (double)(NBINS - 1);
            double kj = exp(-c * c / 0.1);         // restores cancelled k_j
            double ws = kj * atomicAdd(&g_acc[j], 0.0);
            double nm = kj * atomicAdd(&g_acc[NBINS + j], 0.0);
            if (ws != 0.0) loss += fabs(nm) / (ws + 1e-8);
        }
        float res = (float)(loss / NBINS);
        for (int i = 0; i < out_size; i++) out[i] = res;
        for (int k = 0; k < NACC; k++) g_acc[k] = 0.0;
        g_count = 0u;
        __threadfence();
    }
}

extern "C" void kernel_launch(void* const* d_in, const int* in_sizes, int n_in,
                              void* d_out, int out_size) {
    const float* preds = (const float*)d_in[0];
    const float* targs = (const float*)d_in[1];
    int n = in_sizes[0];
    // 148 SMs x 8 CTAs/SM = one full wave at occupancy 8
    ace_fused_kernel<<<1184, 128>>>(preds, targs, n, (float*)d_out, out_size);
}

// round 6
// speedup vs baseline: 1.6618x; 1.6618x over previous
#include <cuda_runtime.h>

#define NBINS 20
#define NHALF 10
#define NACC  (2 * NBINS)   // g_acc[0..19] = sum w ; g_acc[20..39] = sum w*(p-t)
#define STAGES 4
#define TPB 128

__device__ double g_acc[NACC];
__device__ unsigned int g_count;

// ---- packed f32x2 helpers (Blackwell FFMA2 path, PTX-only) ----
__device__ __forceinline__ unsigned long long pk2(float lo, float hi) {
    unsigned long long r;
    asm("mov.b64 %0, {%1, %2};" : "=l"(r)
        : "r"(__float_as_uint(lo)), "r"(__float_as_uint(hi)));
    return r;
}
__device__ __forceinline__ void upk2(unsigned long long v, float& lo, float& hi) {
    unsigned int a, b;
    asm("mov.b64 {%0, %1}, %2;" : "=r"(a), "=r"(b) : "l"(v));
    lo = __uint_as_float(a);
    hi = __uint_as_float(b);
}
__device__ __forceinline__ unsigned long long fma2(unsigned long long a,
                                                   unsigned long long b,
                                                   unsigned long long c) {
    unsigned long long d;
    asm("fma.rn.f32x2 %0, %1, %2, %3;" : "=l"(d) : "l"(a), "l"(b), "l"(c));
    return d;
}
__device__ __forceinline__ unsigned long long add2(unsigned long long a,
                                                   unsigned long long b) {
    unsigned long long d;
    asm("add.rn.f32x2 %0, %1, %2;" : "=l"(d) : "l"(a), "l"(b));
    return d;
}
__device__ __forceinline__ unsigned long long mul2(unsigned long long a,
                                                   unsigned long long b) {
    unsigned long long d;
    asm("mul.rn.f32x2 %0, %1, %2;" : "=l"(d) : "l"(a), "l"(b));
    return d;
}

// ---- cp.async helpers ----
__device__ __forceinline__ unsigned int smem_u32(const void* p) {
    unsigned int a;
    asm("{ .reg .u64 t; cvta.to.shared.u64 t, %1; cvt.u32.u64 %0, t; }"
        : "=r"(a) : "l"(p));
    return a;
}
__device__ __forceinline__ void cpa16(unsigned int smem_dst, const void* gsrc) {
    asm volatile("cp.async.cg.shared.global [%0], [%1], 16;"
                 :: "r"(smem_dst), "l"(gsrc));
}
__device__ __forceinline__ void cpa_commit() {
    asm volatile("cp.async.commit_group;");
}
template <int N>
__device__ __forceinline__ void cpa_wait() {
    asm volatile("cp.async.wait_group %0;" :: "n"(N));
}

// delta = 1/19, T = 0.1:
//   r          = exp(2*delta*p/T)  = exp(p * 20/19)
//   lane0 seed = exp(-p^2/T)       = exp(-10 p^2)
//   lane1 seed = seed * r^10       = exp(-10 p^2 + p * 200/19)   (direct MUFU)
#define KR   (20.0f / 19.0f)
#define KR10 (200.0f / 19.0f)

__global__ void __launch_bounds__(TPB, 6)
ace_fused_kernel(const float* __restrict__ preds,
                 const float* __restrict__ targs,
                 int n, float* __restrict__ out, int out_size) {
    __shared__ float4 sp[STAGES][TPB];
    __shared__ float4 st[STAGES][TPB];

    // Packed accumulators: lane0 = bin j, lane1 = bin j+10.
    unsigned long long A2[NHALF], D2[NHALF];
#pragma unroll
    for (int j = 0; j < NHALF; j++) { A2[j] = 0ull; D2[j] = 0ull; }

    const int n4 = n >> 2;
    const float4* p4 = (const float4*)preds;
    const float4* t4 = (const float4*)targs;
    const int stride = gridDim.x * blockDim.x;
    const int tid = threadIdx.x;
    const int g0 = blockIdx.x * blockDim.x + tid;

    // number of grid-stride iterations this thread performs
    const int cnt = (g0 < n4) ? ((n4 - 1 - g0) / stride + 1) : 0;

    unsigned int sp_base = smem_u32(&sp[0][tid]);
    unsigned int st_base = smem_u32(&st[0][tid]);
    const unsigned int stage_bytes = TPB * sizeof(float4);

    // prologue: fill STAGES-1 stages
#pragma unroll
    for (int i = 0; i < STAGES - 1; i++) {
        if (i < cnt) {
            const float4* ps = p4 + g0 + (long long)i * stride;
            const float4* ts = t4 + g0 + (long long)i * stride;
            cpa16(sp_base + i * stage_bytes, ps);
            cpa16(st_base + i * stage_bytes, ts);
        }
        cpa_commit();
    }

    for (int i = 0; i < cnt; i++) {
        cpa_wait<STAGES - 2>();   // stage i's group has landed
        int slot = i & (STAGES - 1);
        float4 pv = sp[slot][tid];
        float4 tv = st[slot][tid];

        // issue prefetch for i + STAGES-1 into the slot we just freed
        {
            int ip = i + STAGES - 1;
            if (ip < cnt) {
                int ps_slot = ip & (STAGES - 1);
                const float4* ps = p4 + g0 + (long long)ip * stride;
                const float4* ts = t4 + g0 + (long long)ip * stride;
                cpa16(sp_base + ps_slot * stage_bytes, ps);
                cpa16(st_base + ps_slot * stage_bytes, ts);
            }
            cpa_commit();
        }

        // process the 4 elements as two 2-element groups (R4 sweet spot)
#pragma unroll
        for (int grp = 0; grp < 2; grp++) {
            float pa = grp ? pv.z : pv.x;
            float pb = grp ? pv.w : pv.y;
            float ta = grp ? tv.z : tv.x;
            float tb = grp ? tv.w : tv.y;

            float qa = pa * pa;
            float qb = pb * pb;
            float sa_lo = __expf(-10.0f * qa);
            float sb_lo = __expf(-10.0f * qb);
            float sa_hi = __expf(fmaf(KR10, pa, -10.0f * qa));
            float sb_hi = __expf(fmaf(KR10, pb, -10.0f * qb));
            float ra = __expf(KR * pa);
            float rb = __expf(KR * pb);
            float da = pa - ta;
            float db = pb - tb;

            unsigned long long sA = pk2(sa_lo, sa_hi);
            unsigned long long sB = pk2(sb_lo, sb_hi);
            unsigned long long rA = pk2(ra, ra);
            unsigned long long rB = pk2(rb, rb);
            unsigned long long dA = pk2(da, da);
            unsigned long long dB = pk2(db, db);

#pragma unroll
            for (int j = 0; j < NHALF; j++) {
                A2[j] = add2(A2[j], sA);
                D2[j] = fma2(sA, dA, D2[j]);
                A2[j] = add2(A2[j], sB);
                D2[j] = fma2(sB, dB, D2[j]);
                if (j < NHALF - 1) {
                    sA = mul2(sA, rA);
                    sB = mul2(sB, rB);
                }
            }
        }
    }
    cpa_wait<0>();   // drain

    // ---- scalar tail (n % 4; empty for this shape) ----
    {
        int base4 = n4 << 2;
        int rem = n - base4;
        if (blockIdx.x == 0 && tid < rem) {
            float p0 = preds[base4 + tid];
            float t0 = targs[base4 + tid];
            float s = __expf(-10.0f * p0 * p0);
            float r = __expf(KR * p0);
            float d = p0 - t0;
            for (int j = 0; j < NBINS; j++) {
                atomicAdd(&g_acc[j],         (double)s);
                atomicAdd(&g_acc[NBINS + j], (double)(s * d));
                s *= r;
            }
        }
    }

    // ---- block reduction: warp shuffles, then shared across warps ----
    __shared__ float sh[4][NACC];
    int lane = tid & 31;
    int warp = tid >> 5;

#pragma unroll
    for (int j = 0; j < NHALF; j++) {
        float alo, ahi, dlo, dhi;
        upk2(A2[j], alo, ahi);
        upk2(D2[j], dlo, dhi);
        float v[4] = {alo, ahi, dlo, dhi};
        // bin indices: A: j, j+10 ; D: 20+j, 30+j
        int idx[4] = {j, j + NHALF, NBINS + j, NBINS + NHALF + j};
#pragma unroll
        for (int q = 0; q < 4; q++) {
            float s = v[q];
#pragma unroll
            for (int off = 16; off; off >>= 1)
                s += __shfl_down_sync(0xffffffffu, s, off);
            if (lane == 0) sh[warp][idx[q]] = s;
        }
    }
    __syncthreads();

    if (tid < NACC) {
        double v = (double)sh[0][tid] + (double)sh[1][tid] +
                   (double)sh[2][tid] + (double)sh[3][tid];
        atomicAdd(&g_acc[tid], v);
    }
    __syncthreads();

    // ---- last block finalizes, writes out, resets state ----
    __shared__ unsigned int s_is_last;
    if (tid == 0) {
        __threadfence();
        unsigned int old = atomicAdd(&g_count, 1u);
        s_is_last = (old == gridDim.x - 1) ? 1u : 0u;
    }
    __syncthreads();

    if (s_is_last && tid == 0) {
        __threadfence();
        double loss = 0.0;
        for (int j = 0; j < NBINS; j++) {
            double c = (double)j / (double)(NBINS - 1);
            double kj = exp(-c * c / 0.1);         // restores cancelled k_j
            double ws = kj * atomicAdd(&g_acc[j], 0.0);
            double nm = kj * atomicAdd(&g_acc[NBINS + j], 0.0);
            if (ws != 0.0) loss += fabs(nm) / (ws + 1e-8);
        }
        float res = (float)(loss / NBINS);
        for (int i = 0; i < out_size; i++) out[i] = res;
        for (int k = 0; k < NACC; k++) g_acc[k] = 0.0;
        g_count = 0u;
        __threadfence();
    }
}

extern "C" void kernel_launch(void* const* d_in, const int* in_sizes, int n_in,
                              void* d_out, int out_size) {
    const float* preds = (const float*)d_in[0];
    const float* targs = (const float*)d_in[1];
    int n = in_sizes[0];
    // 148 SMs x 6 CTAs/SM = one full wave at occupancy 6
    ace_fused_kernel<<<888, TPB>>>(preds, targs, n, (float*)d_out, out_size);
}

// round 7
// speedup vs baseline: 1.7010x; 1.0236x over previous
#include <cuda_runtime.h>

#define NBINS 20
#define NHALF 10
#define NACC  (2 * NBINS)   // g_acc[0..19] = sum w ; g_acc[20..39] = sum w*(p-t)
#define STAGES 4
#define TPB 128
#define GRID 3552           // 148 SMs x 6 CTAs x 4 waves

__device__ double g_acc[NACC];
__device__ unsigned int g_count;

// ---- packed f32x2 helpers (Blackwell FFMA2 path, PTX-only) ----
__device__ __forceinline__ unsigned long long pk2(float lo, float hi) {
    unsigned long long r;
    asm("mov.b64 %0, {%1, %2};" : "=l"(r)
        : "r"(__float_as_uint(lo)), "r"(__float_as_uint(hi)));
    return r;
}
__device__ __forceinline__ void upk2(unsigned long long v, float& lo, float& hi) {
    unsigned int a, b;
    asm("mov.b64 {%0, %1}, %2;" : "=r"(a), "=r"(b) : "l"(v));
    lo = __uint_as_float(a);
    hi = __uint_as_float(b);
}
__device__ __forceinline__ unsigned long long fma2(unsigned long long a,
                                                   unsigned long long b,
                                                   unsigned long long c) {
    unsigned long long d;
    asm("fma.rn.f32x2 %0, %1, %2, %3;" : "=l"(d) : "l"(a), "l"(b), "l"(c));
    return d;
}
__device__ __forceinline__ unsigned long long add2(unsigned long long a,
                                                   unsigned long long b) {
    unsigned long long d;
    asm("add.rn.f32x2 %0, %1, %2;" : "=l"(d) : "l"(a), "l"(b));
    return d;
}
__device__ __forceinline__ unsigned long long mul2(unsigned long long a,
                                                   unsigned long long b) {
    unsigned long long d;
    asm("mul.rn.f32x2 %0, %1, %2;" : "=l"(d) : "l"(a), "l"(b));
    return d;
}

// ---- cp.async helpers ----
__device__ __forceinline__ unsigned int smem_u32(const void* p) {
    unsigned int a;
    asm("{ .reg .u64 t; cvta.to.shared.u64 t, %1; cvt.u32.u64 %0, t; }"
        : "=r"(a) : "l"(p));
    return a;
}
__device__ __forceinline__ void cpa16(unsigned int smem_dst, const void* gsrc) {
    asm volatile("cp.async.cg.shared.global [%0], [%1], 16;"
                 :: "r"(smem_dst), "l"(gsrc));
}
__device__ __forceinline__ void cpa_commit() {
    asm volatile("cp.async.commit_group;");
}
template <int N>
__device__ __forceinline__ void cpa_wait() {
    asm volatile("cp.async.wait_group %0;" :: "n"(N));
}

// delta = 1/19, T = 0.1:
//   r          = exp(2*delta*p/T)  = exp(p * 20/19)
//   lane0 seed = exp(-p^2/T)       = exp(-10 p^2)
//   lane1 seed = seed * r^10       = exp(-10 p^2 + p * 200/19)   (direct MUFU)
#define KR   (20.0f / 19.0f)
#define KR10 (200.0f / 19.0f)

__global__ void __launch_bounds__(TPB, 6)
ace_fused_kernel(const float* __restrict__ preds,
                 const float* __restrict__ targs,
                 int n, float* __restrict__ out, int out_size) {
    __shared__ float4 sp[STAGES][TPB];
    __shared__ float4 st[STAGES][TPB];

    // Packed accumulators: lane0 = bin j, lane1 = bin j+10.
    unsigned long long A2[NHALF], D2[NHALF];
#pragma unroll
    for (int j = 0; j < NHALF; j++) { A2[j] = 0ull; D2[j] = 0ull; }

    const int n4 = n >> 2;
    const float4* p4 = (const float4*)preds;
    const float4* t4 = (const float4*)targs;
    const int stride = gridDim.x * blockDim.x;
    const int tid = threadIdx.x;
    const int g0 = blockIdx.x * blockDim.x + tid;

    // number of grid-stride iterations this thread performs
    const int cnt = (g0 < n4) ? ((n4 - 1 - g0) / stride + 1) : 0;

    unsigned int sp_base = smem_u32(&sp[0][tid]);
    unsigned int st_base = smem_u32(&st[0][tid]);
    const unsigned int stage_bytes = TPB * sizeof(float4);

    // prologue: fill STAGES-1 stages
#pragma unroll
    for (int i = 0; i < STAGES - 1; i++) {
        if (i < cnt) {
            const float4* ps = p4 + g0 + (long long)i * stride;
            const float4* ts = t4 + g0 + (long long)i * stride;
            cpa16(sp_base + i * stage_bytes, ps);
            cpa16(st_base + i * stage_bytes, ts);
        }
        cpa_commit();
    }

    for (int i = 0; i < cnt; i++) {
        cpa_wait<STAGES - 2>();   // stage i's group has landed
        int slot = i & (STAGES - 1);
        float4 pv = sp[slot][tid];
        float4 tv = st[slot][tid];

        // issue prefetch for i + STAGES-1 into the slot we just freed
        {
            int ip = i + STAGES - 1;
            if (ip < cnt) {
                int ps_slot = ip & (STAGES - 1);
                const float4* ps = p4 + g0 + (long long)ip * stride;
                const float4* ts = t4 + g0 + (long long)ip * stride;
                cpa16(sp_base + ps_slot * stage_bytes, ps);
                cpa16(st_base + ps_slot * stage_bytes, ts);
            }
            cpa_commit();
        }

        // process the 4 elements as two 2-element groups (R4 sweet spot)
#pragma unroll
        for (int grp = 0; grp < 2; grp++) {
            float pa = grp ? pv.z : pv.x;
            float pb = grp ? pv.w : pv.y;
            float ta = grp ? tv.z : tv.x;
            float tb = grp ? tv.w : tv.y;

            float qa = pa * pa;
            float qb = pb * pb;
            float sa_lo = __expf(-10.0f * qa);
            float sb_lo = __expf(-10.0f * qb);
            float sa_hi = __expf(fmaf(KR10, pa, -10.0f * qa));
            float sb_hi = __expf(fmaf(KR10, pb, -10.0f * qb));
            float ra = __expf(KR * pa);
            float rb = __expf(KR * pb);
            float da = pa - ta;
            float db = pb - tb;

            unsigned long long sA = pk2(sa_lo, sa_hi);
            unsigned long long sB = pk2(sb_lo, sb_hi);
            unsigned long long rA = pk2(ra, ra);
            unsigned long long rB = pk2(rb, rb);
            unsigned long long dA = pk2(da, da);
            unsigned long long dB = pk2(db, db);

#pragma unroll
            for (int j = 0; j < NHALF; j++) {
                A2[j] = add2(A2[j], sA);
                D2[j] = fma2(sA, dA, D2[j]);
                A2[j] = add2(A2[j], sB);
                D2[j] = fma2(sB, dB, D2[j]);
                if (j < NHALF - 1) {
                    sA = mul2(sA, rA);
                    sB = mul2(sB, rB);
                }
            }
        }
    }
    cpa_wait<0>();   // drain

    // ---- scalar tail (n % 4; empty for this shape) ----
    {
        int base4 = n4 << 2;
        int rem = n - base4;
        if (blockIdx.x == 0 && tid < rem) {
            float p0 = preds[base4 + tid];
            float t0 = targs[base4 + tid];
            float s = __expf(-10.0f * p0 * p0);
            float r = __expf(KR * p0);
            float d = p0 - t0;
            for (int j = 0; j < NBINS; j++) {
                atomicAdd(&g_acc[j],         (double)s);
                atomicAdd(&g_acc[NBINS + j], (double)(s * d));
                s *= r;
            }
        }
    }

    // ---- block reduction: warp shuffles, then shared across warps ----
    __shared__ float sh[4][NACC];
    int lane = tid & 31;
    int warp = tid >> 5;

#pragma unroll
    for (int j = 0; j < NHALF; j++) {
        float alo, ahi, dlo, dhi;
        upk2(A2[j], alo, ahi);
        upk2(D2[j], dlo, dhi);
        float v[4] = {alo, ahi, dlo, dhi};
        // bin indices: A: j, j+10 ; D: 20+j, 30+j
        int idx[4] = {j, j + NHALF, NBINS + j, NBINS + NHALF + j};
#pragma unroll
        for (int q = 0; q < 4; q++) {
            float s = v[q];
#pragma unroll
            for (int off = 16; off; off >>= 1)
                s += __shfl_down_sync(0xffffffffu, s, off);
            if (lane == 0) sh[warp][idx[q]] = s;
        }
    }
    __syncthreads();

    if (tid < NACC) {
        double v = (double)sh[0][tid] + (double)sh[1][tid] +
                   (double)sh[2][tid] + (double)sh[3][tid];
        atomicAdd(&g_acc[tid], v);
    }
    __syncthreads();

    // ---- last block finalizes, writes out, resets state ----
    __shared__ unsigned int s_is_last;
    if (tid == 0) {
        __threadfence();
        unsigned int old = atomicAdd(&g_count, 1u);
        s_is_last = (old == gridDim.x - 1) ? 1u : 0u;
    }
    __syncthreads();

    if (s_is_last && tid == 0) {
        __threadfence();
        double loss = 0.0;
        for (int j = 0; j < NBINS; j++) {
            double c = (double)j / (double)(NBINS - 1);
            double kj = exp(-c * c / 0.1);         // restores cancelled k_j
            double ws = kj * atomicAdd(&g_acc[j], 0.0);
            double nm = kj * atomicAdd(&g_acc[NBINS + j], 0.0);
            if (ws != 0.0) loss += fabs(nm) / (ws + 1e-8);
        }
        float res = (float)(loss / NBINS);
        for (int i = 0; i < out_size; i++) out[i] = res;
        for (int k = 0; k < NACC; k++) g_acc[k] = 0.0;
        g_count = 0u;
        __threadfence();
    }
}

extern "C" void kernel_launch(void* const* d_in, const int* in_sizes, int n_in,
                              void* d_out, int out_size) {
    const float* preds = (const float*)d_in[0];
    const float* targs = (const float*)d_in[1];
    int n = in_sizes[0];
    // 4 waves at 6 CTAs/SM: amortizes single-wave CTA spread via work-stealing
    ace_fused_kernel<<<GRID, TPB>>>(preds, targs, n, (float*)d_out, out_size);
}

// round 8
// speedup vs baseline: 1.7241x; 1.0136x over previous
#include <cuda_runtime.h>
#include <math.h>

#define K_CHEB 14
#define NM 14                 // M~_k, k=1..14  -> g_acc[0..13]   (M_0 = n, exact)
#define NNC 15                // N~_k, k=0..14  -> g_acc[14..28]
#define NACC 29
#define NBINS 20
#define STAGES 4
#define TPB 128
#define GRID (148 * 5 * 5)    // 5 CTAs/SM x 5 waves

__device__ double g_acc[NACC];
__device__ unsigned int g_count;

// ---- packed f32x2 helpers ----
__device__ __forceinline__ unsigned long long pk2(float lo, float hi) {
    unsigned long long r;
    asm("mov.b64 %0, {%1, %2};" : "=l"(r)
        : "r"(__float_as_uint(lo)), "r"(__float_as_uint(hi)));
    return r;
}
__device__ __forceinline__ void upk2(unsigned long long v, float& lo, float& hi) {
    unsigned int a, b;
    asm("mov.b64 {%0, %1}, %2;" : "=r"(a), "=r"(b) : "l"(v));
    lo = __uint_as_float(a);
    hi = __uint_as_float(b);
}
__device__ __forceinline__ unsigned long long fma2(unsigned long long a,
                                                   unsigned long long b,
                                                   unsigned long long c) {
    unsigned long long d;
    asm("fma.rn.f32x2 %0, %1, %2, %3;" : "=l"(d) : "l"(a), "l"(b), "l"(c));
    return d;
}
__device__ __forceinline__ unsigned long long add2(unsigned long long a,
                                                   unsigned long long b) {
    unsigned long long d;
    asm("add.rn.f32x2 %0, %1, %2;" : "=l"(d) : "l"(a), "l"(b));
    return d;
}
__device__ __forceinline__ unsigned long long mul2(unsigned long long a,
                                                   unsigned long long b) {
    unsigned long long d;
    asm("mul.rn.f32x2 %0, %1, %2;" : "=l"(d) : "l"(a), "l"(b));
    return d;
}

// ---- cp.async helpers ----
__device__ __forceinline__ unsigned int smem_u32(const void* p) {
    unsigned int a;
    asm("{ .reg .u64 t; cvta.to.shared.u64 t, %1; cvt.u32.u64 %0, t; }"
        : "=r"(a) : "l"(p));
    return a;
}
__device__ __forceinline__ void cpa16(unsigned int smem_dst, const void* gsrc) {
    asm volatile("cp.async.cg.shared.global [%0], [%1], 16;"
                 :: "r"(smem_dst), "l"(gsrc));
}
__device__ __forceinline__ void cpa_commit() {
    asm volatile("cp.async.commit_group;");
}
template <int N>
__device__ __forceinline__ void cpa_wait() {
    asm volatile("cp.async.wait_group %0;" :: "n"(N));
}

__device__ __forceinline__ double wred_d(double v) {
#pragma unroll
    for (int off = 16; off; off >>= 1)
        v += __shfl_down_sync(0xffffffffu, v, off);
    return v;
}

// Sign pattern sigma_k for S_k = sigma_k * T_k, sigma = + + - - + + - - ...
// Recurrence: S_{k+1} = m_k * S_k + S_{k-1}, m_k = +2u for odd k+1, -2u for even k+1.
__global__ void __launch_bounds__(TPB, 5)
ace_cheb_kernel(const float* __restrict__ preds,
                const float* __restrict__ targs,
                int n, float* __restrict__ out, int out_size) {
    __shared__ float4 sp[STAGES][TPB];
    __shared__ float4 st[STAGES][TPB];

    // Packed accumulators (elements-in-lanes): MMr[k-1] = sum S_k, NNr[k] = sum S_k*(p-t)
    unsigned long long MMr[NM], NNr[NNC];
#pragma unroll
    for (int j = 0; j < NM; j++) MMr[j] = 0ull;
#pragma unroll
    for (int j = 0; j < NNC; j++) NNr[j] = 0ull;

    const unsigned long long ONE2 = pk2(1.0f, 1.0f);
    const unsigned long long NEG1 = pk2(-1.0f, -1.0f);

    const int n4 = n >> 2;
    const float4* p4 = (const float4*)preds;
    const float4* t4 = (const float4*)targs;
    const int stride = gridDim.x * blockDim.x;
    const int tid = threadIdx.x;
    const int g0 = blockIdx.x * blockDim.x + tid;
    const int cnt = (g0 < n4) ? ((n4 - 1 - g0) / stride + 1) : 0;

    unsigned int sp_base = smem_u32(&sp[0][tid]);
    unsigned int st_base = smem_u32(&st[0][tid]);
    const unsigned int stage_bytes = TPB * sizeof(float4);

#pragma unroll
    for (int i = 0; i < STAGES - 1; i++) {
        if (i < cnt) {
            cpa16(sp_base + i * stage_bytes, p4 + g0 + (long long)i * stride);
            cpa16(st_base + i * stage_bytes, t4 + g0 + (long long)i * stride);
        }
        cpa_commit();
    }

    for (int i = 0; i < cnt; i++) {
        cpa_wait<STAGES - 2>();
        int slot = i & (STAGES - 1);
        float4 pv = sp[slot][tid];
        float4 tv = st[slot][tid];
        {
            int ip = i + STAGES - 1;
            if (ip < cnt) {
                int ps = ip & (STAGES - 1);
                cpa16(sp_base + ps * stage_bytes, p4 + g0 + (long long)ip * stride);
                cpa16(st_base + ps * stage_bytes, t4 + g0 + (long long)ip * stride);
            }
            cpa_commit();
        }

#pragma unroll
        for (int grp = 0; grp < 2; grp++) {
            float pa = grp ? pv.z : pv.x;
            float pb = grp ? pv.w : pv.y;
            float ta = grp ? tv.z : tv.x;
            float tb = grp ? tv.w : tv.y;

            float ua = fmaf(2.0f, pa, -1.0f);
            float ub = fmaf(2.0f, pb, -1.0f);
            float da = pa - ta;
            float db = pb - tb;

            unsigned long long uu = pk2(ua, ub);
            unsigned long long dd = pk2(da, db);
            unsigned long long u2 = add2(uu, uu);           // +2u
            unsigned long long nu2 = mul2(u2, NEG1);        // -2u

            NNr[0] = add2(NNr[0], dd);                      // N_0 += d   (S_0 = 1)
            MMr[0] = add2(MMr[0], uu);                      // M_1 += u   (S_1 = u)
            NNr[1] = fma2(uu, dd, NNr[1]);                  // N_1 += u*d

            unsigned long long Sp = ONE2;                   // S_0
            unsigned long long Sc = uu;                     // S_1
#pragma unroll
            for (int k = 2; k <= K_CHEB; k++) {
                unsigned long long Sn = fma2((k & 1) ? u2 : nu2, Sc, Sp);
                Sp = Sc; Sc = Sn;
                MMr[k - 1] = add2(MMr[k - 1], Sc);
                NNr[k]     = fma2(Sc, dd, NNr[k]);
            }
        }
    }
    cpa_wait<0>();

    // ---- scalar tail (n % 4; empty for this shape) ----
    {
        int base4 = n4 << 2;
        int rem = n - base4;
        if (blockIdx.x == 0 && tid < rem) {
            float p0 = preds[base4 + tid];
            float t0 = targs[base4 + tid];
            double u = 2.0 * p0 - 1.0;
            double d = (double)p0 - (double)t0;
            atomicAdd(&g_acc[14], d);            // N_0
            atomicAdd(&g_acc[0], u);             // M~_1
            atomicAdd(&g_acc[15], u * d);        // N~_1
            double Sp = 1.0, Sc = u;
            for (int k = 2; k <= K_CHEB; k++) {
                double m = (k & 1) ? 2.0 * u : -2.0 * u;
                double Sn = m * Sc + Sp;
                Sp = Sc; Sc = Sn;
                atomicAdd(&g_acc[k - 1], Sc);
                atomicAdd(&g_acc[14 + k], Sc * d);
            }
        }
    }

    // ---- block reduction: warp shuffles, shared across warps, double atomics ----
    __shared__ float sh[4][NACC];
    int lane = tid & 31;
    int warp = tid >> 5;

#pragma unroll
    for (int k = 0; k < NACC; k++) {
        unsigned long long v = (k < NM) ? MMr[k] : NNr[k - NM];
        float lo, hi;
        upk2(v, lo, hi);
        float s = lo + hi;
#pragma unroll
        for (int off = 16; off; off >>= 1)
            s += __shfl_down_sync(0xffffffffu, s, off);
        if (lane == 0) sh[warp][k] = s;
    }
    __syncthreads();

    if (tid < NACC) {
        double v = (double)sh[0][tid] + (double)sh[1][tid] +
                   (double)sh[2][tid] + (double)sh[3][tid];
        atomicAdd(&g_acc[tid], v);
    }
    __syncthreads();

    // ---- last block finalizes ----
    __shared__ unsigned int s_is_last;
    if (tid == 0) {
        __threadfence();
        unsigned int old = atomicAdd(&g_count, 1u);
        s_is_last = (old == gridDim.x - 1) ? 1u : 0u;
    }
    __syncthreads();

    if (s_is_last) {
        __shared__ double mAcc[NACC];
        __shared__ double sA[NBINS], sD[NBINS];
        if (tid < NACC) mAcc[tid] = atomicAdd(&g_acc[tid], 0.0);
        if (tid < NBINS) { sA[tid] = 0.0; sD[tid] = 0.0; }
        __syncthreads();

        // 128-point Chebyshev quadrature: thread tid handles node m = tid
        const double PI_D = 3.14159265358979323846;
        double theta = (tid + 0.5) * (PI_D / 128.0);
        double um = cos(theta);
        double G = (double)n;          // M_0 = n exactly
        double H = mAcc[14];           // N_0
#pragma unroll
        for (int k = 1; k <= K_CHEB; k++) {
            double sg = ((k >> 1) & 1) ? -1.0 : 1.0;   // sigma_k, pattern ++--
            double ck = 2.0 * cos(k * theta) * sg;
            G += ck * mAcc[k - 1];
            H += ck * mAcc[14 + k];
        }
        G *= (1.0 / 128.0);
        H *= (1.0 / 128.0);
        double pm = 0.5 * (um + 1.0);

        for (int j = 0; j < NBINS; j++) {
            double cj = (double)j / 19.0;
            double w = exp(-10.0 * (pm - cj) * (pm - cj));
            double a = wred_d(w * G);
            double d = wred_d(w * H);
            if (lane == 0) { atomicAdd(&sA[j], a); atomicAdd(&sD[j], d); }
        }
        __syncthreads();

        if (tid == 0) {
            double loss = 0.0;
            for (int j = 0; j < NBINS; j++) {
                double ws = sA[j];
                if (ws != 0.0) loss += fabs(sD[j]) / (ws + 1e-8);
            }
            float res = (float)(loss / NBINS);
            for (int i = 0; i < out_size; i++) out[i] = res;
            for (int k = 0; k < NACC; k++) g_acc[k] = 0.0;
            g_count = 0u;
            __threadfence();
        }
    }
}

extern "C" void kernel_launch(void* const* d_in, const int* in_sizes, int n_in,
                              void* d_out, int out_size) {
    const float* preds = (const float*)d_in[0];
    const float* targs = (const float*)d_in[1];
    int n = in_sizes[0];
    ace_cheb_kernel<<<GRID, TPB>>>(preds, targs, n, (float*)d_out, out_size);
}

// round 9
// speedup vs baseline: 1.8446x; 1.0699x over previous
#include <cuda_runtime.h>
#include <math.h>

#define K_CHEB 12
#define NM 12                 // M~_k, k=1..12  -> g_acc[0..11]   (M_0 = n, exact)
#define NNC 13                // N~_k, k=0..12  -> g_acc[12..24]
#define NACC 25
#define NBINS 20
#define STAGES 4
#define TPB 128
#define GRID (148 * 6 * 4)    // 6 CTAs/SM x 4 waves

__device__ double g_acc[NACC];
__device__ unsigned int g_count;

// ---- cp.async helpers ----
__device__ __forceinline__ unsigned int smem_u32(const void* p) {
    unsigned int a;
    asm("{ .reg .u64 t; cvta.to.shared.u64 t, %1; cvt.u32.u64 %0, t; }"
        : "=r"(a) : "l"(p));
    return a;
}
__device__ __forceinline__ void cpa16(unsigned int smem_dst, const void* gsrc) {
    asm volatile("cp.async.cg.shared.global [%0], [%1], 16;"
                 :: "r"(smem_dst), "l"(gsrc));
}
__device__ __forceinline__ void cpa_commit() {
    asm volatile("cp.async.commit_group;");
}
template <int N>
__device__ __forceinline__ void cpa_wait() {
    asm volatile("cp.async.wait_group %0;" :: "n"(N));
}

__device__ __forceinline__ double wred_d(double v) {
#pragma unroll
    for (int off = 16; off; off >>= 1)
        v += __shfl_down_sync(0xffffffffu, v, off);
    return v;
}
__device__ __forceinline__ float wred_f(float v) {
#pragma unroll
    for (int off = 16; off; off >>= 1)
        v += __shfl_down_sync(0xffffffffu, v, off);
    return v;
}

// S_k = sigma_k * T_k(u), sigma pattern per k: + - - + + - - ... (sg = ((k>>1)&1) ? - : +)
// Recurrence: S_k = m * S_{k-1} + S_{k-2}, m = +2u for odd k, -2u for even k.
__global__ void __launch_bounds__(TPB, 6)
ace_cheb_kernel(const float* __restrict__ preds,
                const float* __restrict__ targs,
                int n, float* __restrict__ out, int out_size) {
    __shared__ float4 sp[STAGES][TPB];
    __shared__ float4 st[STAGES][TPB];

    // Scalar accumulators: M[k-1] = sum S_k (k=1..12), N[k] = sum S_k*(p-t) (k=0..12)
    float M[NM], N[NNC];
#pragma unroll
    for (int j = 0; j < NM; j++) M[j] = 0.0f;
#pragma unroll
    for (int j = 0; j < NNC; j++) N[j] = 0.0f;

    const int n4 = n >> 2;
    const float4* p4 = (const float4*)preds;
    const float4* t4 = (const float4*)targs;
    const int stride = gridDim.x * blockDim.x;
    const int tid = threadIdx.x;
    const int g0 = blockIdx.x * blockDim.x + tid;
    const int cnt = (g0 < n4) ? ((n4 - 1 - g0) / stride + 1) : 0;

    unsigned int sp_base = smem_u32(&sp[0][tid]);
    unsigned int st_base = smem_u32(&st[0][tid]);
    const unsigned int stage_bytes = TPB * sizeof(float4);

#pragma unroll
    for (int i = 0; i < STAGES - 1; i++) {
        if (i < cnt) {
            cpa16(sp_base + i * stage_bytes, p4 + g0 + (long long)i * stride);
            cpa16(st_base + i * stage_bytes, t4 + g0 + (long long)i * stride);
        }
        cpa_commit();
    }

    for (int i = 0; i < cnt; i++) {
        cpa_wait<STAGES - 2>();
        int slot = i & (STAGES - 1);
        float4 pv = sp[slot][tid];
        float4 tv = st[slot][tid];
        {
            int ip = i + STAGES - 1;
            if (ip < cnt) {
                int ps = ip & (STAGES - 1);
                cpa16(sp_base + ps * stage_bytes, p4 + g0 + (long long)ip * stride);
                cpa16(st_base + ps * stage_bytes, t4 + g0 + (long long)ip * stride);
            }
            cpa_commit();
        }

#pragma unroll
        for (int e = 0; e < 4; e++) {
            float p = (e == 0) ? pv.x : (e == 1) ? pv.y : (e == 2) ? pv.z : pv.w;
            float t = (e == 0) ? tv.x : (e == 1) ? tv.y : (e == 2) ? tv.z : tv.w;

            float u   = fmaf(2.0f, p, -1.0f);
            float d   = p - t;
            float u2  = u + u;
            float nu2 = -u2;

            N[0] += d;                     // S_0 = 1
            M[0] += u;                     // S_1 = u
            N[1] = fmaf(u, d, N[1]);

            float Sp = 1.0f, Sc = u;
#pragma unroll
            for (int k = 2; k <= K_CHEB; k++) {
                float Sn = fmaf((k & 1) ? u2 : nu2, Sc, Sp);
                Sp = Sc; Sc = Sn;
                M[k - 1] += Sc;
                N[k] = fmaf(Sc, d, N[k]);
            }
        }
    }
    cpa_wait<0>();

    // ---- scalar tail (n % 4; empty for this shape) ----
    {
        int base4 = n4 << 2;
        int rem = n - base4;
        if (blockIdx.x == 0 && tid < rem) {
            float p0 = preds[base4 + tid];
            float t0 = targs[base4 + tid];
            double u = 2.0 * p0 - 1.0;
            double d = (double)p0 - (double)t0;
            atomicAdd(&g_acc[NM], d);            // N_0
            atomicAdd(&g_acc[0], u);             // M~_1
            atomicAdd(&g_acc[NM + 1], u * d);    // N~_1
            double Sp = 1.0, Sc = u;
            for (int k = 2; k <= K_CHEB; k++) {
                double m = (k & 1) ? 2.0 * u : -2.0 * u;
                double Sn = m * Sc + Sp;
                Sp = Sc; Sc = Sn;
                atomicAdd(&g_acc[k - 1], Sc);
                atomicAdd(&g_acc[NM + k], Sc * d);
            }
        }
    }

    // ---- block reduction: warp shuffles, shared across warps, double atomics ----
    __shared__ float sh[4][NACC];
    int lane = tid & 31;
    int warp = tid >> 5;

#pragma unroll
    for (int k = 0; k < NACC; k++) {
        float s = wred_f((k < NM) ? M[k] : N[k - NM]);
        if (lane == 0) sh[warp][k] = s;
    }
    __syncthreads();

    if (tid < NACC) {
        double v = (double)sh[0][tid] + (double)sh[1][tid] +
                   (double)sh[2][tid] + (double)sh[3][tid];
        atomicAdd(&g_acc[tid], v);
    }
    __syncthreads();

    // ---- last block finalizes ----
    __shared__ unsigned int s_is_last;
    if (tid == 0) {
        __threadfence();
        unsigned int old = atomicAdd(&g_count, 1u);
        s_is_last = (old == gridDim.x - 1) ? 1u : 0u;
    }
    __syncthreads();

    if (s_is_last) {
        __shared__ double mAcc[NACC];
        __shared__ double sA[NBINS], sD[NBINS];
        if (tid < NACC) mAcc[tid] = atomicAdd(&g_acc[tid], 0.0);
        if (tid < NBINS) { sA[tid] = 0.0; sD[tid] = 0.0; }
        __syncthreads();

        // 128-point Chebyshev quadrature: thread tid handles node m = tid
        const double PI_D = 3.14159265358979323846;
        double theta = (tid + 0.5) * (PI_D / 128.0);
        double um = cos(theta);
        double G = (double)n;          // M_0 = n exactly
        double H = mAcc[NM];           // N_0
#pragma unroll
        for (int k = 1; k <= K_CHEB; k++) {
            double sg = ((k >> 1) & 1) ? -1.0 : 1.0;   // sigma_k
            double ck = 2.0 * cos(k * theta) * sg;
            G += ck * mAcc[k - 1];
            H += ck * mAcc[NM + k];
        }
        G *= (1.0 / 128.0);
        H *= (1.0 / 128.0);
        double pm = 0.5 * (um + 1.0);

        for (int j = 0; j < NBINS; j++) {
            double cj = (double)j / 19.0;
            double w = exp(-10.0 * (pm - cj) * (pm - cj));
            double a = wred_d(w * G);
            double d = wred_d(w * H);
            if (lane == 0) { atomicAdd(&sA[j], a); atomicAdd(&sD[j], d); }
        }
        __syncthreads();

        if (tid == 0) {
            double loss = 0.0;
            for (int j = 0; j < NBINS; j++) {
                double ws = sA[j];
                if (ws != 0.0) loss += fabs(sD[j]) / (ws + 1e-8);
            }
            float res = (float)(loss / NBINS);
            for (int i = 0; i < out_size; i++) out[i] = res;
            for (int k = 0; k < NACC; k++) g_acc[k] = 0.0;
            g_count = 0u;
            __threadfence();
        }
    }
}

extern "C" void kernel_launch(void* const* d_in, const int* in_sizes, int n_in,
                              void* d_out, int out_size) {
    const float* preds = (const float*)d_in[0];
    const float* targs = (const float*)d_in[1];
    int n = in_sizes[0];
    ace_cheb_kernel<<<GRID, TPB>>>(preds, targs, n, (float*)d_out, out_size);
}

// round 11
// speedup vs baseline: 2.3133x; 1.2541x over previous
#include <cuda_runtime.h>
#include <math.h>

#define NB 4096
#define NBINS 20
#define TPB 256
#define GRID 444          // 148 SMs x 3 CTAs, one balanced wave
#define NACC 40           // g_acc[0..19] = A~_j (no kappa), [20..39] = D~_j

#define CNT_SHIFT 41
#define DBIAS (1 << 22)                  // per-element bias on fixed-point d
#define DSCALE 2097152.0f                // 2^21
#define DINV (1.0f / 2097152.0f)
#define SUM_MASK ((1ULL << CNT_SHIFT) - 1ULL)

__device__ double g_acc[NACC];
__device__ unsigned int g_count;

__device__ __forceinline__ float wred_f(float v) {
#pragma unroll
    for (int off = 16; off; off >>= 1)
        v += __shfl_down_sync(0xffffffffu, v, off);
    return v;
}

__global__ void __launch_bounds__(TPB)
ace_hist_kernel(const float* __restrict__ preds,
                const float* __restrict__ targs,
                int n, float* __restrict__ out, int out_size) {
    __shared__ unsigned long long hist[NB];
    const int tid = threadIdx.x;

    for (int b = tid; b < NB; b += TPB) hist[b] = 0ull;
    __syncthreads();

    // ---- main loop: one packed 64-bit shared atomic per element ----
    const int n4 = n >> 2;
    const float4* p4 = (const float4*)preds;
    const float4* t4 = (const float4*)targs;
    const int stride = gridDim.x * blockDim.x;
    int g = blockIdx.x * blockDim.x + tid;

    if (g < n4) {
        float4 pv = p4[g];
        float4 tv = t4[g];
        while (1) {
            int gn = g + stride;
            bool more = (gn < n4);
            float4 pn, tn;
            if (more) { pn = p4[gn]; tn = t4[gn]; }   // 1-ahead prefetch

#pragma unroll
            for (int e = 0; e < 4; e++) {
                float p = (e == 0) ? pv.x : (e == 1) ? pv.y : (e == 2) ? pv.z : pv.w;
                float t = (e == 0) ? tv.x : (e == 1) ? tv.y : (e == 2) ? tv.z : tv.w;
                float d = p - t;
                int b = (int)(p * (float)NB);
                b = min(b, NB - 1);
                int ds = __float2int_rn(d * DSCALE);
                unsigned long long v =
                    (1ULL << CNT_SHIFT) +
                    (unsigned long long)(unsigned int)(ds + DBIAS);
                atomicAdd(&hist[b], v);               // no return use -> REDS
            }

            if (!more) break;
            pv = pn; tv = tn; g = gn;
        }
    }

    // ---- scalar tail (n % 4): CTA 0 folds into its own histogram ----
    {
        int base4 = n4 << 2;
        int rem = n - base4;
        if (blockIdx.x == 0 && tid < rem) {
            float p = preds[base4 + tid];
            float t = targs[base4 + tid];
            float d = p - t;
            int b = min((int)(p * (float)NB), NB - 1);
            int ds = __float2int_rn(d * DSCALE);
            unsigned long long v =
                (1ULL << CNT_SHIFT) +
                (unsigned long long)(unsigned int)(ds + DBIAS);
            atomicAdd(&hist[b], v);
        }
    }
    __syncthreads();

    // ---- per-CTA epilogue: fold local histogram into 40 moments ----
    // w_j(c_b) = exp(-10 c_b^2) * rho_b^j * kappa_j ; kappa_j applied at finalize
    float A[NBINS], D[NBINS];
#pragma unroll
    for (int j = 0; j < NBINS; j++) { A[j] = 0.0f; D[j] = 0.0f; }

    for (int b = tid; b < NB; b += TPB) {     // 16 bins per thread
        unsigned long long v = hist[b];
        if (v == 0ull) continue;
        unsigned int cnt_u = (unsigned int)(v >> CNT_SHIFT);
        long long sumd = (long long)(v & SUM_MASK) - ((long long)cnt_u << 22);
        float cnt = (float)cnt_u;
        float Dv = (float)sumd * DINV;
        float cb = ((float)b + 0.5f) * (1.0f / (float)NB);
        float w   = __expf(-10.0f * cb * cb);       // base_b
        float rho = __expf(cb * (20.0f / 19.0f));   // exp(20 c_b /19)
#pragma unroll
        for (int j = 0; j < NBINS; j++) {
            A[j] = fmaf(w, cnt, A[j]);
            D[j] = fmaf(w, Dv, D[j]);
            w *= rho;
        }
    }

    // ---- block reduction: warp shuffles -> shared -> global double atomics ----
    __shared__ float sh[TPB / 32][NACC];
    int lane = tid & 31;
    int warp = tid >> 5;

#pragma unroll
    for (int k = 0; k < NACC; k++) {
        float s = wred_f((k < NBINS) ? A[k] : D[k - NBINS]);
        if (lane == 0) sh[warp][k] = s;
    }
    __syncthreads();

    if (tid < NACC) {
        double v = 0.0;
#pragma unroll
        for (int w2 = 0; w2 < TPB / 32; w2++) v += (double)sh[w2][tid];
        atomicAdd(&g_acc[tid], v);
    }
    __syncthreads();

    // ---- last CTA finalizes ----
    __shared__ unsigned int s_is_last;
    if (tid == 0) {
        __threadfence();
        unsigned int old = atomicAdd(&g_count, 1u);
        s_is_last = (old == gridDim.x - 1) ? 1u : 0u;
    }
    __syncthreads();

    if (s_is_last) {
        __shared__ double sloss[NBINS];
        if (tid < NBINS) {
            __threadfence();
            double Aj = atomicAdd(&g_acc[tid], 0.0);
            double Dj = atomicAdd(&g_acc[NBINS + tid], 0.0);
            double cj = (double)tid / 19.0;
            double kappa = exp(-10.0 * cj * cj);
            double ws = kappa * Aj;
            sloss[tid] = (ws != 0.0) ? fabs(kappa * Dj) / (ws + 1e-8) : 0.0;
        }
        __syncthreads();
        if (tid == 0) {
            double loss = 0.0;
            for (int j = 0; j < NBINS; j++) loss += sloss[j];
            float res = (float)(loss / NBINS);
            for (int i = 0; i < out_size; i++) out[i] = res;
            for (int k = 0; k < NACC; k++) g_acc[k] = 0.0;
            g_count = 0u;
            __threadfence();
        }
    }
}

extern "C" void kernel_launch(void* const* d_in, const int* in_sizes, int n_in,
                              void* d_out, int out_size) {
    const float* preds = (const float*)d_in[0];
    const float* targs = (const float*)d_in[1];
    int n = in_sizes[0];
    ace_hist_kernel<<<GRID, TPB>>>(preds, targs, n, (float*)d_out, out_size);
}

// round 13
// speedup vs baseline: 2.7838x; 1.2034x over previous
#include <cuda_runtime.h>
#include <math.h>

#define NB 512
#define NBINS 20
#define TPB 256
#define GRID 2664         // 148 SMs x 6 CTAs x 3 waves
#define NACC 40           // g_acc[0..19] = A~_j (no kappa), [20..39] = D~_j

#define CNT_INC (1u << 24)
#define SUM_MASK 0xFFFFFFu
#define DS_SCALE 16384.0f          // 2^14
#define DS_INV (1.0f / 16384.0f)
#define DS_BIAS 32768              // 2^15 per element

__device__ double g_acc[NACC];
__device__ unsigned int g_count;

__device__ __forceinline__ float wred_f(float v) {
#pragma unroll
    for (int off = 16; off; off >>= 1)
        v += __shfl_down_sync(0xffffffffu, v, off);
    return v;
}

__global__ void __launch_bounds__(TPB, 6)
ace_hist_kernel(const float* __restrict__ preds,
                const float* __restrict__ targs,
                int n, float* __restrict__ out, int out_size) {
    __shared__ unsigned int hist[NB];
    __shared__ float smA[NBINS], smD[NBINS];
    const int tid = threadIdx.x;

    for (int b = tid; b < NB; b += TPB) hist[b] = 0u;
    if (tid < NBINS) { smA[tid] = 0.0f; smD[tid] = 0.0f; }
    __syncthreads();

    // ---- main loop: one 32-bit shared atomic per element ----
    const int n4 = n >> 2;
    const float4* p4 = (const float4*)preds;
    const float4* t4 = (const float4*)targs;
    const int stride = gridDim.x * blockDim.x;
    int g = blockIdx.x * blockDim.x + tid;

    if (g < n4) {
        float4 pv = p4[g];
        float4 tv = t4[g];
        while (1) {
            int gn = g + stride;
            bool more = (gn < n4);
            float4 pn, tn;
            if (more) { pn = p4[gn]; tn = t4[gn]; }   // 1-ahead prefetch

#pragma unroll
            for (int e = 0; e < 4; e++) {
                float p = (e == 0) ? pv.x : (e == 1) ? pv.y : (e == 2) ? pv.z : pv.w;
                float t = (e == 0) ? tv.x : (e == 1) ? tv.y : (e == 2) ? tv.z : tv.w;
                int b = (int)(p * (float)NB);
                b = min(max(b, 0), NB - 1);
                int ds = __float2int_rn((p - t) * DS_SCALE);
                atomicAdd(&hist[b],
                          CNT_INC + (unsigned int)(ds + DS_BIAS));   // REDS.32
            }

            if (!more) break;
            pv = pn; tv = tn; g = gn;
        }
    }

    // ---- scalar tail (n % 4): CTA 0 folds into its own histogram ----
    {
        int base4 = n4 << 2;
        int rem = n - base4;
        if (blockIdx.x == 0 && tid < rem) {
            float p = preds[base4 + tid];
            float t = targs[base4 + tid];
            int b = min(max((int)(p * (float)NB), 0), NB - 1);
            int ds = __float2int_rn((p - t) * DS_SCALE);
            atomicAdd(&hist[b], CNT_INC + (unsigned int)(ds + DS_BIAS));
        }
    }
    __syncthreads();

    // ---- per-CTA epilogue: fold 512-bin histogram into 40 moments ----
    // Each thread owns 2 bins (tid, tid+256). Warp-reduce per moment,
    // lane0 accumulates into shared; minimal register pressure.
    {
        int b0 = tid;
        int b1 = tid + TPB;

        unsigned int v0 = hist[b0];
        unsigned int v1 = hist[b1];
        float cnt0 = (float)(v0 >> 24);
        float cnt1 = (float)(v1 >> 24);
        float Dv0 = ((float)(int)((v0 & SUM_MASK) - ((v0 >> 24) << 15))) * DS_INV;
        float Dv1 = ((float)(int)((v1 & SUM_MASK) - ((v1 >> 24) << 15))) * DS_INV;

        float c0 = ((float)b0 + 0.5f) * (1.0f / (float)NB);
        float c1 = ((float)b1 + 0.5f) * (1.0f / (float)NB);
        float w0   = __expf(-10.0f * c0 * c0);
        float w1   = __expf(-10.0f * c1 * c1);
        float rho0 = __expf(c0 * (20.0f / 19.0f));
        float rho1 = __expf(c1 * (20.0f / 19.0f));

        int lane = tid & 31;
#pragma unroll
        for (int j = 0; j < NBINS; j++) {
            float a = fmaf(w0, cnt0, w1 * cnt1);
            float d = fmaf(w0, Dv0, w1 * Dv1);
            a = wred_f(a);
            d = wred_f(d);
            if (lane == 0) {
                atomicAdd(&smA[j], a);
                atomicAdd(&smD[j], d);
            }
            w0 *= rho0;
            w1 *= rho1;
        }
    }
    __syncthreads();

    if (tid < NACC) {
        double v = (tid < NBINS) ? (double)smA[tid] : (double)smD[tid - NBINS];
        atomicAdd(&g_acc[tid], v);
    }
    __syncthreads();

    // ---- last CTA finalizes ----
    __shared__ unsigned int s_is_last;
    if (tid == 0) {
        __threadfence();
        unsigned int old = atomicAdd(&g_count, 1u);
        s_is_last = (old == gridDim.x - 1) ? 1u : 0u;
    }
    __syncthreads();

    if (s_is_last) {
        __shared__ double sloss[NBINS];
        if (tid < NBINS) {
            __threadfence();
            double Aj = atomicAdd(&g_acc[tid], 0.0);
            double Dj = atomicAdd(&g_acc[NBINS + tid], 0.0);
            double cj = (double)tid / 19.0;
            double kappa = exp(-10.0 * cj * cj);
            double ws = kappa * Aj;
            sloss[tid] = (ws != 0.0) ? fabs(kappa * Dj) / (ws + 1e-8) : 0.0;
        }
        __syncthreads();
        if (tid == 0) {
            double loss = 0.0;
            for (int j = 0; j < NBINS; j++) loss += sloss[j];
            float res = (float)(loss / NBINS);
            for (int i = 0; i < out_size; i++) out[i] = res;
            for (int k = 0; k < NACC; k++) g_acc[k] = 0.0;
            g_count = 0u;
            __threadfence();
        }
    }
}

extern "C" void kernel_launch(void* const* d_in, const int* in_sizes, int n_in,
                              void* d_out, int out_size) {
    const float* preds = (const float*)d_in[0];
    const float* targs = (const float*)d_in[1];
    int n = in_sizes[0];
    ace_hist_kernel<<<GRID, TPB>>>(preds, targs, n, (float*)d_out, out_size);
}